// round 15
// baseline (speedup 1.0000x reference)
#include <cuda_runtime.h>
#include <cuda_bf16.h>
#include <cstdint>
#include <math.h>

#define DIM    256
#define HEADS  8
#define HD     32
#define N1V    256
#define N2V    256
#define BTOT   256
#define NWIN   128
#define TBL    1575
#define MTOT   (BTOT * N1V)

typedef unsigned long long ull;

// ---------------- scratch (device globals; no allocation) ----------------
__device__ float d_qh [MTOT * DIM];              // scaled Q proj
__device__ float d_kvh[MTOT * 2 * DIM];          // K|V proj
__device__ float d_x  [MTOT * DIM];              // attention output
__device__ float d_biasF[HEADS * N1V * N2V];     // expanded rel-pos bias (2MB)

// ---------------- packed f32x2 helpers ----------------
__device__ __forceinline__ ull pack2(float x, float y) {
    ull r; asm("mov.b64 %0, {%1, %2};" : "=l"(r) : "f"(x), "f"(y)); return r;
}
__device__ __forceinline__ void unpack2(ull v, float& x, float& y) {
    asm("mov.b64 {%0, %1}, %2;" : "=f"(x), "=f"(y) : "l"(v));
}
__device__ __forceinline__ void ffma2(ull& d, ull a, ull b) {
    asm("fma.rn.f32x2 %0, %1, %2, %0;" : "+l"(d) : "l"(a), "l"(b));
}

// ---------------- FFMA2 NT SGEMM, 128x64 tile, 3 blocks/SM -----------------
__global__ void __launch_bounds__(256, 3) gemm_nt(
    const float* __restrict__ A, const float* __restrict__ B,
    const float* __restrict__ bias, float* __restrict__ C,
    int M, int N, int K, float alpha)
{
    __shared__ float As[2][16][132];
    __shared__ float Bs[2][16][68];
    const int m0  = blockIdx.y * 128;
    const int n0  = blockIdx.x * 64;
    const int tid = threadIdx.x;
    const int tr  = tid >> 4;
    const int tc  = tid & 15;

    int lrA[2], lcA[2];
#pragma unroll
    for (int i = 0; i < 2; i++) {
        int li = tid + i * 256;
        lrA[i] = li >> 2;
        lcA[i] = (li & 3) << 2;
    }
    const int lrB = tid >> 2;
    const int lcB = (tid & 3) << 2;

    ull acc2[4][4];
#pragma unroll
    for (int i = 0; i < 4; i++)
#pragma unroll
        for (int j = 0; j < 4; j++) acc2[i][j] = 0ull;

    const int NT = K >> 4;

#pragma unroll
    for (int i = 0; i < 2; i++) {
        float4 va = *(const float4*)(A + (size_t)(m0 + lrA[i]) * K + lcA[i]);
        As[0][lcA[i] + 0][lrA[i]] = va.x; As[0][lcA[i] + 1][lrA[i]] = va.y;
        As[0][lcA[i] + 2][lrA[i]] = va.z; As[0][lcA[i] + 3][lrA[i]] = va.w;
    }
    {
        float4 vb = *(const float4*)(B + (size_t)(n0 + lrB) * K + lcB);
        Bs[0][lcB + 0][lrB] = vb.x; Bs[0][lcB + 1][lrB] = vb.y;
        Bs[0][lcB + 2][lrB] = vb.z; Bs[0][lcB + 3][lrB] = vb.w;
    }
    __syncthreads();

#pragma unroll 1
    for (int kt = 0; kt < NT; kt++) {
        const int cur = kt & 1;
        float4 na[2], nb;
        const bool more = (kt + 1 < NT);
        if (more) {
            const int k0 = (kt + 1) << 4;
#pragma unroll
            for (int i = 0; i < 2; i++)
                na[i] = *(const float4*)(A + (size_t)(m0 + lrA[i]) * K + k0 + lcA[i]);
            nb = *(const float4*)(B + (size_t)(n0 + lrB) * K + k0 + lcB);
        }
#pragma unroll
        for (int kk = 0; kk < 16; kk++) {
            float4 a04 = *(const float4*)&As[cur][kk][tr * 8];
            float4 a48 = *(const float4*)&As[cur][kk][tr * 8 + 4];
            float4 bq  = *(const float4*)&Bs[cur][kk][tc * 4];
            ull ap[4];
            ap[0] = pack2(a04.x, a04.y); ap[1] = pack2(a04.z, a04.w);
            ap[2] = pack2(a48.x, a48.y); ap[3] = pack2(a48.z, a48.w);
            ull b2[4];
            b2[0] = pack2(bq.x, bq.x); b2[1] = pack2(bq.y, bq.y);
            b2[2] = pack2(bq.z, bq.z); b2[3] = pack2(bq.w, bq.w);
#pragma unroll
            for (int mi = 0; mi < 4; mi++)
#pragma unroll
                for (int n = 0; n < 4; n++)
                    ffma2(acc2[mi][n], ap[mi], b2[n]);
        }
        if (more) {
            const int nxt = cur ^ 1;
#pragma unroll
            for (int i = 0; i < 2; i++) {
                As[nxt][lcA[i] + 0][lrA[i]] = na[i].x; As[nxt][lcA[i] + 1][lrA[i]] = na[i].y;
                As[nxt][lcA[i] + 2][lrA[i]] = na[i].z; As[nxt][lcA[i] + 3][lrA[i]] = na[i].w;
            }
            Bs[nxt][lcB + 0][lrB] = nb.x; Bs[nxt][lcB + 1][lrB] = nb.y;
            Bs[nxt][lcB + 2][lrB] = nb.z; Bs[nxt][lcB + 3][lrB] = nb.w;
            __syncthreads();
        }
    }

    float b4[4];
#pragma unroll
    for (int n = 0; n < 4; n++) b4[n] = bias[n0 + tc * 4 + n];
#pragma unroll
    for (int mi = 0; mi < 4; mi++) {
        int r = m0 + tr * 8 + 2 * mi;
        float4 v0, v1;
        float x, y;
        unpack2(acc2[mi][0], x, y); v0.x = alpha * (x + b4[0]); v1.x = alpha * (y + b4[0]);
        unpack2(acc2[mi][1], x, y); v0.y = alpha * (x + b4[1]); v1.y = alpha * (y + b4[1]);
        unpack2(acc2[mi][2], x, y); v0.z = alpha * (x + b4[2]); v1.z = alpha * (y + b4[2]);
        unpack2(acc2[mi][3], x, y); v0.w = alpha * (x + b4[3]); v1.w = alpha * (y + b4[3]);
        *(float4*)(C + (size_t)r * N + n0 + tc * 4)       = v0;
        *(float4*)(C + (size_t)(r + 1) * N + n0 + tc * 4) = v1;
    }
}

// ---------------- rel-pos bias expansion: biasF[h][q][k] -------------------
__global__ void __launch_bounds__(256) bias_pre(
    const float* __restrict__ btab_g, const int* __restrict__ rel,
    float* __restrict__ biasF)
{
    int idx = blockIdx.x * 256 + threadIdx.x;
    int ri  = rel[idx] * HEADS;
#pragma unroll
    for (int h = 0; h < HEADS; h++)
        biasF[h * (N1V * N2V) + idx] = btab_g[ri + h];
}

// ---------------- attention v7: 8qx8k QK, direct mask/bias, 3 barriers -----
// QK: warp = one 8-query group (qg=tid>>5), kg=tid&31 -> keys kj=32j+kg.
// PV (unchanged v4): thread (tid>>4, tid&15) -> 4 queries x dims {2kg,2kg+1}.
#define SK 36
#define SQ 36
#define SP 260
#define KV_OFF 0
#define PB_OFF (256 * SK)                        // 9216 floats
#define ATTN_SMEM_FLOATS (PB_OFF + 64 * SP)      // 25856 floats
#define ATTN_SMEM_BYTES (ATTN_SMEM_FLOATS * 4)   // 103424 B -> 2 blocks/SM

__global__ void __launch_bounds__(256, 2) attn_kernel(
    const float* __restrict__ qh, const float* __restrict__ kvh,
    const float* __restrict__ mask, const float* __restrict__ biasF,
    float* __restrict__ xout)
{
    extern __shared__ float smem[];
    float* Ks = smem + KV_OFF;     // K tile, later V tile
    float* Pb = smem + PB_OFF;     // Qs alias, then P
    float* Qs = Pb;

    const int tid = threadIdx.x;
    const int qg  = tid >> 5;      // 0..7  (warp id)
    const int kg  = tid & 31;      // 0..31 (lane)
    const int q0  = blockIdx.x * 64;
    const int h   = blockIdx.y;
    const int b   = blockIdx.z;
    const int w   = b & (NWIN - 1);
    const int qi0 = qg * 8;

    // ---- load Q (64x32, into Pb head) and K (256x32) ----
    {
        const float* qbase = qh + ((size_t)(b * N1V + q0)) * DIM + h * HD;
#pragma unroll
        for (int i = 0; i < 2; i++) {
            int li = tid + i * 256;
            int r  = li >> 3;
            int c4 = (li & 7) * 4;
            *(float4*)&Qs[r * SQ + c4] =
                *(const float4*)(qbase + (size_t)r * DIM + c4);
        }
        const float* kbase = kvh + ((size_t)b * N2V) * (2 * DIM) + h * HD;
#pragma unroll
        for (int i = 0; i < 8; i++) {
            int li = tid + i * 256;
            int r  = li >> 3;
            int c4 = (li & 7) * 4;
            *(float4*)&Ks[r * SK + c4] =
                *(const float4*)(kbase + (size_t)r * (2 * DIM) + c4);
        }
    }
    __syncthreads();

    // ---- QK: s[8][8]; Q reads are warp-broadcast, K bytes/MAC halved ----
    float s[8][8];
#pragma unroll
    for (int i = 0; i < 8; i++)
#pragma unroll
        for (int j = 0; j < 8; j++) s[i][j] = 0.f;

#pragma unroll 1
    for (int c4 = 0; c4 < 8; c4++) {
        float q4[8][4];
#pragma unroll
        for (int i = 0; i < 8; i++) {
            float4 v = *(const float4*)&Qs[(qi0 + i) * SQ + c4 * 4];
            q4[i][0] = v.x; q4[i][1] = v.y; q4[i][2] = v.z; q4[i][3] = v.w;
        }
#pragma unroll
        for (int j = 0; j < 8; j++) {
            float4 kv = *(const float4*)&Ks[(32 * j + kg) * SK + c4 * 4];
#pragma unroll
            for (int i = 0; i < 8; i++) {
                s[i][j] = fmaf(q4[i][0], kv.x, s[i][j]);
                s[i][j] = fmaf(q4[i][1], kv.y, s[i][j]);
                s[i][j] = fmaf(q4[i][2], kv.z, s[i][j]);
                s[i][j] = fmaf(q4[i][3], kv.w, s[i][j]);
            }
        }
    }
    __syncthreads();   // Q/K reads done -> V may overwrite Ks, P may use Pb

    // ---- load V (over K); latency hides under mask/bias/softmax ----
    {
        const float* vbase = kvh + ((size_t)b * N2V) * (2 * DIM) + DIM + h * HD;
#pragma unroll
        for (int i = 0; i < 8; i++) {
            int li = tid + i * 256;
            int r  = li >> 3;
            int c4 = (li & 7) * 4;
            *(float4*)&Ks[r * SK + c4] =
                *(const float4*)(vbase + (size_t)r * (2 * DIM) + c4);
        }
    }

    // ---- mask + bias direct from gmem (128B-coalesced per (q,j)) ----
    {
        const float* maskb = mask  + ((size_t)(w * N1V + q0 + qi0)) * N2V + kg;
        const float* biasb = biasF + ((size_t)(h * N1V + q0 + qi0)) * N2V + kg;
#pragma unroll
        for (int i = 0; i < 8; i++)
#pragma unroll
            for (int j = 0; j < 8; j++)
                s[i][j] += maskb[(size_t)i * N2V + 32 * j]
                         + biasb[(size_t)i * N2V + 32 * j];
    }

    // ---- softmax: per-query max/sum over 8 local + full-warp bfly ----
    float linv[8];
#pragma unroll
    for (int i = 0; i < 8; i++) {
        float mx = s[i][0];
#pragma unroll
        for (int j = 1; j < 8; j++) mx = fmaxf(mx, s[i][j]);
        mx = fmaxf(mx, __shfl_xor_sync(0xFFFFFFFFu, mx, 1));
        mx = fmaxf(mx, __shfl_xor_sync(0xFFFFFFFFu, mx, 2));
        mx = fmaxf(mx, __shfl_xor_sync(0xFFFFFFFFu, mx, 4));
        mx = fmaxf(mx, __shfl_xor_sync(0xFFFFFFFFu, mx, 8));
        mx = fmaxf(mx, __shfl_xor_sync(0xFFFFFFFFu, mx, 16));
        float ls = 0.f;
#pragma unroll
        for (int j = 0; j < 8; j++) {
            float e = __expf(s[i][j] - mx);
            s[i][j] = e;
            ls += e;
        }
        ls += __shfl_xor_sync(0xFFFFFFFFu, ls, 1);
        ls += __shfl_xor_sync(0xFFFFFFFFu, ls, 2);
        ls += __shfl_xor_sync(0xFFFFFFFFu, ls, 4);
        ls += __shfl_xor_sync(0xFFFFFFFFu, ls, 8);
        ls += __shfl_xor_sync(0xFFFFFFFFu, ls, 16);
        linv[i] = 1.0f / ls;
    }

    // ---- store P (1/l folded); lanes write consecutive floats ----
#pragma unroll
    for (int i = 0; i < 8; i++)
#pragma unroll
        for (int j = 0; j < 8; j++)
            Pb[(qi0 + i) * SP + 32 * j + kg] = s[i][j] * linv[i];
    __syncthreads();   // covers P stores AND the V STS above

    // ---- PV (v4 mapping): thread (qg4, kg16) -> 4 queries x 2 dims ----
    const int qg4 = tid >> 4;
    const int kg16 = tid & 15;
    const int qj0 = qg4 * 4;
    float o[4][2];
#pragma unroll
    for (int i = 0; i < 4; i++) { o[i][0] = 0.f; o[i][1] = 0.f; }

#pragma unroll 4
    for (int k4 = 0; k4 < 64; k4++) {
        float p[4][4];
#pragma unroll
        for (int i = 0; i < 4; i++) {
            float4 v = *(const float4*)&Pb[(qj0 + i) * SP + k4 * 4];
            p[i][0] = v.x; p[i][1] = v.y; p[i][2] = v.z; p[i][3] = v.w;
        }
#pragma unroll
        for (int kk = 0; kk < 4; kk++) {
            float2 vv = *(const float2*)&Ks[(k4 * 4 + kk) * SK + 2 * kg16];
#pragma unroll
            for (int i = 0; i < 4; i++) {
                o[i][0] = fmaf(p[i][kk], vv.x, o[i][0]);
                o[i][1] = fmaf(p[i][kk], vv.y, o[i][1]);
            }
        }
    }

    // ---- write O ----
#pragma unroll
    for (int i = 0; i < 4; i++) {
        float2 v; v.x = o[i][0]; v.y = o[i][1];
        *(float2*)(xout + ((size_t)(b * N1V + q0 + qj0 + i)) * DIM
                   + h * HD + 2 * kg16) = v;
    }
}

// ---------------- launch ----------------
extern "C" void kernel_launch(void* const* d_in, const int* in_sizes, int n_in,
                              void* d_out, int out_size)
{
    const float* q    = (const float*)d_in[0];
    const float* kv   = (const float*)d_in[1];
    const float* mask = (const float*)d_in[2];
    const float* Wq   = (const float*)d_in[3];
    const float* bq   = (const float*)d_in[4];
    const float* Wkv  = (const float*)d_in[5];
    const float* bkv  = (const float*)d_in[6];
    const float* btab = (const float*)d_in[7];
    const float* Wp   = (const float*)d_in[8];
    const float* bp   = (const float*)d_in[9];
    const int*   rel  = (const int*)d_in[10];
    float* out = (float*)d_out;

    static float* qh  = nullptr;
    static float* kvh = nullptr;
    static float* xb  = nullptr;
    static float* bF  = nullptr;
    if (!qh) {
        cudaGetSymbolAddress((void**)&qh,  d_qh);
        cudaGetSymbolAddress((void**)&kvh, d_kvh);
        cudaGetSymbolAddress((void**)&xb,  d_x);
        cudaGetSymbolAddress((void**)&bF,  d_biasF);
        cudaFuncSetAttribute(attn_kernel,
                             cudaFuncAttributeMaxDynamicSharedMemorySize,
                             ATTN_SMEM_BYTES);
    }

    const int M = MTOT;
    const float scale = 0.17677669529663687f;       // 1/sqrt(32)

    bias_pre<<<N1V * N2V / 256, 256>>>(btab, rel, bF);
    gemm_nt<<<dim3(DIM / 64, M / 128), 256>>>(q, Wq, bq, qh, M, DIM, DIM, scale);
    gemm_nt<<<dim3((2 * DIM) / 64, M / 128), 256>>>(kv, Wkv, bkv, kvh, M, 2 * DIM, DIM, 1.f);
    attn_kernel<<<dim3(4, HEADS, BTOT), 256, ATTN_SMEM_BYTES>>>(qh, kvh, mask, bF, xb);
    gemm_nt<<<dim3(DIM / 64, M / 128), 256>>>(xb, Wp, bp, out, M, DIM, DIM, 1.f);
}